// round 15
// baseline (speedup 1.0000x reference)
#include <cuda_runtime.h>
#include <cuda_bf16.h>
#include <math.h>
#include <stdint.h>

#define BB 256
#define TT 64
#define HH 1024
#define GG 4096
#define VV 128
#define LL 32

// ---------------- device state (no allocations allowed) ----------------
__device__ __align__(16) float d_hbuf[2][BB * HH];           // fp32 h
__device__ __align__(16) __nv_bfloat16 d_hbb[2][BB * HH];    // bf16 big part of h
__device__ __align__(16) __nv_bfloat16 d_hsb[2][BB * HH];    // bf16 residual of h
__device__ __align__(16) float d_cbuf[BB * HH];
__device__ __align__(16) float d_encX[VV * GG];              // [v][ku*4+g] = emb@W + b
__device__ __align__(16) float d_decX[VV * GG];
__device__ int d_tok[BB];
__device__ __align__(16) __nv_bfloat16 d_Ubb[2][(size_t)GG * HH];  // [which][pc][k] big
__device__ __align__(16) __nv_bfloat16 d_Usb[2][(size_t)GG * HH];  // residual

// ---------------- helpers ----------------
__device__ __forceinline__ float sigmoidf_(float x) { return 1.0f / (1.0f + __expf(-x)); }
__device__ __forceinline__ float tanhf_(float x) {
    float a = fabsf(x);
    float e = __expf(2.0f * a);
    return copysignf(1.0f - 2.0f / (e + 1.0f), x);
}
__device__ __forceinline__ uint32_t smem_u32(const void* p) {
    uint32_t a;
    asm("{ .reg .u64 t; cvta.to.shared.u64 t, %1; cvt.u32.u64 %0, t; }" : "=r"(a) : "l"(p));
    return a;
}
__device__ __forceinline__ void cpasync16(uint32_t dst, const void* src) {
    asm volatile("cp.async.cg.shared.global [%0], [%1], 16;"
                 :: "r"(dst), "l"(__cvta_generic_to_global(src)) : "memory");
}
__device__ __forceinline__ void mma16816(float* c, const uint32_t* a, const uint32_t* b) {
    asm volatile(
        "mma.sync.aligned.m16n8k16.row.col.f32.bf16.bf16.f32 "
        "{%0,%1,%2,%3}, {%4,%5,%6,%7}, {%8,%9}, {%0,%1,%2,%3};"
        : "+f"(c[0]), "+f"(c[1]), "+f"(c[2]), "+f"(c[3])
        : "r"(a[0]), "r"(a[1]), "r"(a[2]), "r"(a[3]), "r"(b[0]), "r"(b[1]));
}
__device__ __forceinline__ void ldsm4(uint32_t* r, uint32_t addr) {
    asm volatile("ldmatrix.sync.aligned.m8n8.x4.shared.b16 {%0,%1,%2,%3}, [%4];"
                 : "=r"(r[0]), "=r"(r[1]), "=r"(r[2]), "=r"(r[3]) : "r"(addr));
}

// ---------------- init ----------------
__global__ void init_kernel() {
    int n = BB * HH;
    __nv_bfloat16 z = __float2bfloat16(0.0f);
    for (int i = blockIdx.x * blockDim.x + threadIdx.x; i < n; i += gridDim.x * blockDim.x) {
        d_hbuf[0][i] = 0.0f;
        d_hbb[0][i] = z;
        d_hsb[0][i] = z;
        d_cbuf[i] = 0.0f;
    }
    if (blockIdx.x == 0 && threadIdx.x < BB) d_tok[threadIdx.x] = VV - 1;
}

// ---------------- table: Xp[v][ku*4+g] = emb[v]@W[:,g*1024+ku] + b ----------------
__global__ __launch_bounds__(256, 1) void table_kernel(
    const float* __restrict__ emb, const float* __restrict__ W,
    const float* __restrict__ bias, int which) {
    float* Xp = which ? d_decX : d_encX;
    __shared__ __align__(16) float semb[32][VV];
    int tid = threadIdx.x;
    int c = blockIdx.x * 32 + (tid & 31);
    int vg = tid >> 5;
    float acc[16];
#pragma unroll
    for (int j = 0; j < 16; j++) acc[j] = 0.0f;
    for (int r0 = 0; r0 < HH; r0 += 32) {
#pragma unroll
        for (int j = 0; j < 4; j++) {
            int idx4 = tid + 256 * j;
            int v = idx4 >> 3, rq = idx4 & 7;
            float4 t4 = *(const float4*)&emb[(size_t)v * HH + r0 + (rq << 2)];
            semb[(rq << 2) + 0][v] = t4.x;
            semb[(rq << 2) + 1][v] = t4.y;
            semb[(rq << 2) + 2][v] = t4.z;
            semb[(rq << 2) + 3][v] = t4.w;
        }
        __syncthreads();
#pragma unroll 8
        for (int r = 0; r < 32; r++) {
            float w = W[(size_t)(r0 + r) * GG + c];
            const float* sp = &semb[r][vg << 4];
#pragma unroll
            for (int j = 0; j < 16; j++) acc[j] += sp[j] * w;
        }
        __syncthreads();
    }
    int k = c & (HH - 1), g = c >> 10;
    float bv = bias[c];
#pragma unroll
    for (int j = 0; j < 16; j++) {
        int v = (vg << 4) + j;
        Xp[(size_t)v * GG + (k << 2) + g] = acc[j] + bv;
    }
}

// ---------------- pack U: Upk[ku*4+g][k] = U[k][g*1024+ku], bf16 split ----------------
__global__ __launch_bounds__(256, 4) void pack_kernel(const float* __restrict__ U, int which) {
    __shared__ float s[32][33];
    int tid = threadIdx.x;
    int k0 = blockIdx.x * 32;
    int c0 = blockIdx.y * 32;
#pragma unroll
    for (int j = 0; j < 4; j++) {
        int idx = tid + 256 * j;
        int r = idx >> 5, ci = idx & 31;
        s[r][ci] = U[(size_t)(k0 + r) * GG + c0 + ci];
    }
    __syncthreads();
    int g = c0 >> 10;
    int ku0 = c0 & (HH - 1);
    __nv_bfloat16* Ub = d_Ubb[which];
    __nv_bfloat16* Us = d_Usb[which];
#pragma unroll
    for (int j = 0; j < 4; j++) {
        int idx = tid + 256 * j;
        int ci = idx >> 5, r = idx & 31;
        float v = s[r][ci];
        __nv_bfloat16 bp = __float2bfloat16(v);
        size_t o = (size_t)((ku0 + ci) * 4 + g) * HH + (k0 + r);
        Ub[o] = bp;
        Us[o] = __float2bfloat16(v - __bfloat162float(bp));
    }
}

// ---------------- mma LSTM step (R13 shape + K128 chunks + pipelined LDSM) -------------
// grid (64,2), 512 threads = 16 warps (4m x 4n), warp tile 32(M)x16(N packed).
// CTA: M=128 x N=64 packed; K=1024 in 8 chunks of 128.
// z = hb@Ub + hb@Us + hs@Ub (bf16x3).
#define RSTRB 272          // bytes per smem row (256B data + 16B pad; 272%128=16 -> rotation)
#define APART 34816u       // 128 rows * 272
#define BPART 17408u       // 64 rows * 272
#define OFS_AB 0u
#define OFS_AS 34816u
#define OFS_BBG 69632u
#define OFS_BS 87040u
#define BUFSZ  104448u
#define OFS_TOK 208896u
#define SMEM_BYTES 209408
#define NCHUNK 8
#define ZSTR 68            // z epilogue stride (floats)

__device__ __forceinline__ void stage_chunk(
    uint32_t sb, int buf, int kc, int tid,
    const __nv_bfloat16* hb, const __nv_bfloat16* hs,
    const __nv_bfloat16* Ub, const __nv_bfloat16* Us, int bm0, int bn0) {
    uint32_t base = sb + buf * BUFSZ;
    int kofs = kc * 128;
#pragma unroll
    for (int j = 0; j < 4; j++) {               // A: 128 rows x 256B per part
        int idx = tid + 512 * j;
        int row = idx >> 4, c = idx & 15;
        uint32_t d = (uint32_t)(row * RSTRB + c * 16);
        size_t go = (size_t)(bm0 + row) * HH + kofs + c * 8;
        cpasync16(base + OFS_AB + d, hb + go);
        cpasync16(base + OFS_AS + d, hs + go);
    }
#pragma unroll
    for (int j = 0; j < 2; j++) {               // B: 64 rows x 256B per part
        int idx = tid + 512 * j;
        int row = idx >> 4, c = idx & 15;
        uint32_t d = (uint32_t)(row * RSTRB + c * 16);
        size_t go = (size_t)(bn0 + row) * HH + kofs + c * 8;
        cpasync16(base + OFS_BBG + d, Ub + go);
        cpasync16(base + OFS_BS + d, Us + go);
    }
}

#define LDFRAG(s, ka) do { \
    ldsm4(fa[s][0],  a_base + (ka)); \
    ldsm4(fa[s][1],  a_base + (ka) + 16 * RSTRB); \
    ldsm4(fas[s][0], a_base + (ka) + APART); \
    ldsm4(fas[s][1], a_base + (ka) + APART + 16 * RSTRB); \
    ldsm4(fb[s],     b_base + (ka)); \
    ldsm4(fbs[s],    b_base + (ka) + BPART); \
} while (0)

__global__ __launch_bounds__(512, 1) void lstm_mma_kernel(
    int which, const int* __restrict__ tokptr, int tokstride, int tok_mode, int parity) {
    extern __shared__ char smem[];
    uint32_t sb = smem_u32(smem);
    int tid = threadIdx.x;
    int wid = tid >> 5, lane = tid & 31;
    int wm = wid & 3, wn = wid >> 2;            // 4m x 4n; warp tile rows wm*32, cols wn*16
    int bn0 = blockIdx.x * 64;
    int bm0 = blockIdx.y * 128;

    const __nv_bfloat16* hb = d_hbb[parity];
    const __nv_bfloat16* hs = d_hsb[parity];
    const __nv_bfloat16* Ub = d_Ubb[which];
    const __nv_bfloat16* Us = d_Usb[which];
    int* stok = (int*)(smem + OFS_TOK);

    if (tid < 128)
        stok[tid] = tok_mode ? d_tok[bm0 + tid] : tokptr[(size_t)(bm0 + tid) * tokstride];

    float acc[2][2][4];
#pragma unroll
    for (int mt = 0; mt < 2; mt++)
#pragma unroll
        for (int np = 0; np < 2; np++)
#pragma unroll
            for (int r = 0; r < 4; r++) acc[mt][np][r] = 0.0f;

    // ldmatrix lane bases (canonical x4 mapping)
    uint32_t a_base = sb + OFS_AB +
        (uint32_t)((wm * 32 + (lane & 15)) * RSTRB + (lane >> 4) * 16);
    // B: one ldsm4 covers 16 n-rows x 16 k
    uint32_t b_base = sb + OFS_BBG +
        (uint32_t)((wn * 16 + ((lane >> 4) << 3) + (lane & 7)) * RSTRB + ((lane >> 3) & 1) * 16);

    uint32_t fa[2][2][4], fas[2][2][4], fb[2][4], fbs[2][4];

    stage_chunk(sb, 0, 0, tid, hb, hs, Ub, Us, bm0, bn0);
    asm volatile("cp.async.commit_group;" ::: "memory");

    for (int i = 0; i < NCHUNK; i++) {
        asm volatile("cp.async.wait_group 0;" ::: "memory");
        __syncthreads();
        if (i + 1 < NCHUNK) {
            stage_chunk(sb, (i + 1) & 1, i + 1, tid, hb, hs, Ub, Us, bm0, bn0);
            asm volatile("cp.async.commit_group;" ::: "memory");
        }
        uint32_t bofs = (uint32_t)((i & 1) * BUFSZ);
        LDFRAG(0, bofs);
#pragma unroll
        for (int ks = 0; ks < 8; ks++) {
            int cs = ks & 1;
            if (ks < 7) LDFRAG(cs ^ 1, bofs + (uint32_t)((ks + 1) * 32));
            // term-major: 4 distinct accumulators between reuses
#pragma unroll
            for (int mt = 0; mt < 2; mt++)
#pragma unroll
                for (int np = 0; np < 2; np++)
                    mma16816(acc[mt][np], fa[cs][mt], &fb[cs][np * 2]);
#pragma unroll
            for (int mt = 0; mt < 2; mt++)
#pragma unroll
                for (int np = 0; np < 2; np++)
                    mma16816(acc[mt][np], fa[cs][mt], &fbs[cs][np * 2]);
#pragma unroll
            for (int mt = 0; mt < 2; mt++)
#pragma unroll
                for (int np = 0; np < 2; np++)
                    mma16816(acc[mt][np], fas[cs][mt], &fb[cs][np * 2]);
        }
    }

    // ---- epilogue: z -> smem -> gates ----
    float* z = (float*)smem;   // 128 x ZSTR floats = 34816 B (buffer region, dead now)
    int gq = lane >> 2, tq = lane & 3;
    __syncthreads();
#pragma unroll
    for (int mt = 0; mt < 2; mt++) {
        int row0 = wm * 32 + mt * 16 + gq;
#pragma unroll
        for (int np = 0; np < 2; np++) {
            int col = wn * 16 + np * 8 + 2 * tq;
            *(float2*)&z[row0 * ZSTR + col] = make_float2(acc[mt][np][0], acc[mt][np][1]);
            *(float2*)&z[(row0 + 8) * ZSTR + col] = make_float2(acc[mt][np][2], acc[mt][np][3]);
        }
    }
    __syncthreads();

    int row = tid & 127;
    int ublk = tid >> 7;                 // 0..3 -> units ublk*4 .. +3
    int b = bm0 + row;
    int tok = stok[row];
    const float* Xp = which ? d_decX : d_encX;
    const float* hin = d_hbuf[parity];
    float* hout = d_hbuf[parity ^ 1];
    __nv_bfloat16* hbo = d_hbb[parity ^ 1];
    __nv_bfloat16* hso = d_hsb[parity ^ 1];

    if (tok != 0) {
#pragma unroll
        for (int j = 0; j < 4; j++) {
            int u = ublk * 4 + j;
            int kg = (bn0 >> 2) + u;
            float4 zv = *(const float4*)&z[row * ZSTR + u * 4];
            float4 xv = *(const float4*)&Xp[(size_t)tok * GG + bn0 + u * 4];
            float zi = zv.x + xv.x, zf = zv.y + xv.y;
            float zg = zv.z + xv.z, zo = zv.w + xv.w;
            size_t off = (size_t)b * HH + kg;
            float c2 = sigmoidf_(zf) * d_cbuf[off] + sigmoidf_(zi) * tanhf_(zg);
            float h2 = sigmoidf_(zo) * tanhf_(c2);
            d_cbuf[off] = c2;
            hout[off] = h2;
            __nv_bfloat16 hb1 = __float2bfloat16(h2);
            hbo[off] = hb1;
            hso[off] = __float2bfloat16(h2 - __bfloat162float(hb1));
        }
    } else {
#pragma unroll
        for (int j = 0; j < 4; j++) {
            int u = ublk * 4 + j;
            size_t off = (size_t)b * HH + (bn0 >> 2) + u;
            float h2 = hin[off];
            hout[off] = h2;
            __nv_bfloat16 hb1 = __float2bfloat16(h2);
            hbo[off] = hb1;
            hso[off] = __float2bfloat16(h2 - __bfloat162float(hb1));
        }
    }
}

// ---------------- decoder output: logits -> softmax -> argmax ----------------
__global__ __launch_bounds__(256, 2) void dec_out_kernel(
    const float* __restrict__ outW, const float* __restrict__ outb,
    float* __restrict__ dout, int out_size, int t, int parity) {
    const float* __restrict__ h = d_hbuf[parity];
    __shared__ __align__(16) float sh[4][HH];
    __shared__ float slog[4][VV];
    __shared__ float sexp[4][VV];
    __shared__ float ssum[4];
    __shared__ int   stk[4];

    int tid = threadIdx.x;
    int b0 = blockIdx.x * 4;
#pragma unroll
    for (int j = 0; j < 4; j++) {
        int idx4 = tid + 256 * j;
        int row = idx4 >> 8, c4 = idx4 & 255;
        *(float4*)&sh[row][c4 << 2] = *(const float4*)&h[(size_t)(b0 + row) * HH + (c4 << 2)];
    }
    __syncthreads();

    int v = tid & 127, half = tid >> 7;
    float a0 = 0.0f, a1 = 0.0f;
    const float* s0 = sh[half * 2];
    const float* s1 = sh[half * 2 + 1];
#pragma unroll 8
    for (int k = 0; k < HH; k++) {
        float w = outW[(size_t)k * VV + v];
        a0 += s0[k] * w;
        a1 += s1[k] * w;
    }
    float bv = outb[v];
    slog[half * 2][v]     = a0 + bv;
    slog[half * 2 + 1][v] = a1 + bv;
    __syncthreads();

    if (tid < 128) {
        int rw = tid >> 5, lane = tid & 31;
        float m = -3.4e38f; int am = VV;
#pragma unroll
        for (int i = 0; i < 4; i++) {
            int vv = lane + (i << 5);
            float x = slog[rw][vv];
            if (x > m || (x == m && vv < am)) { m = x; am = vv; }
        }
#pragma unroll
        for (int off = 16; off; off >>= 1) {
            float om = __shfl_down_sync(0xffffffffu, m, off);
            int   oa = __shfl_down_sync(0xffffffffu, am, off);
            if (om > m || (om == m && oa < am)) { m = om; am = oa; }
        }
        m  = __shfl_sync(0xffffffffu, m, 0);
        am = __shfl_sync(0xffffffffu, am, 0);
        float s = 0.0f;
#pragma unroll
        for (int i = 0; i < 4; i++) {
            int vv = lane + (i << 5);
            float e = __expf(slog[rw][vv] - m);
            sexp[rw][vv] = e;
            s += e;
        }
#pragma unroll
        for (int off = 16; off; off >>= 1) s += __shfl_xor_sync(0xffffffffu, s, off);
        if (lane == 0) { ssum[rw] = s; stk[rw] = am; d_tok[b0 + rw] = am; }
    }
    __syncthreads();
#pragma unroll
    for (int j = 0; j < 2; j++) {
        int idx = tid + 256 * j;
        int rw = idx >> 7, vv = idx & 127;
        dout[((size_t)(b0 + rw) * LL + t) * VV + vv] = sexp[rw][vv] / ssum[rw];
    }
    if (out_size >= BB * LL * VV + LL * BB && tid < 4) {
        dout[(size_t)BB * LL * VV + (size_t)t * BB + (b0 + tid)] = (float)stk[tid];
    }
}

// ---------------- launcher ----------------
extern "C" void kernel_launch(void* const* d_in, const int* in_sizes, int n_in,
                              void* d_out, int out_size) {
    int idx = 0;
    const int* inputs = (const int*)d_in[idx++];
    if (idx < n_in && in_sizes[idx] == 1) idx++;  // skip max_len scalar if present
    const float* enc_emb = (const float*)d_in[idx++];
    const float* enc_W   = (const float*)d_in[idx++];
    const float* enc_U   = (const float*)d_in[idx++];
    const float* enc_b   = (const float*)d_in[idx++];
    const float* dec_emb = (const float*)d_in[idx++];
    const float* dec_W   = (const float*)d_in[idx++];
    const float* dec_U   = (const float*)d_in[idx++];
    const float* dec_b   = (const float*)d_in[idx++];
    const float* out_W   = (const float*)d_in[idx++];
    const float* out_b   = (const float*)d_in[idx++];
    float* dout = (float*)d_out;

    cudaFuncSetAttribute(lstm_mma_kernel, cudaFuncAttributeMaxDynamicSharedMemorySize,
                         SMEM_BYTES);

    init_kernel<<<256, 256>>>();
    table_kernel<<<128, 256>>>(enc_emb, enc_W, enc_b, 0);
    table_kernel<<<128, 256>>>(dec_emb, dec_W, dec_b, 1);
    pack_kernel<<<dim3(32, 128), 256>>>(enc_U, 0);
    pack_kernel<<<dim3(32, 128), 256>>>(dec_U, 1);

    dim3 grid(64, 2);
    int par = 0;
    for (int t = 0; t < TT; t++) {
        lstm_mma_kernel<<<grid, 512, SMEM_BYTES>>>(0, inputs + t, TT, 0, par);
        par ^= 1;
    }
    for (int s = 0; s < LL; s++) {
        lstm_mma_kernel<<<grid, 512, SMEM_BYTES>>>(1, (const int*)0, 1, 1, par);
        par ^= 1;
        dec_out_kernel<<<64, 256>>>(out_W, out_b, dout, out_size, s, par);
    }
}

// round 16
// speedup vs baseline: 1.0992x; 1.0992x over previous
#include <cuda_runtime.h>
#include <cuda_bf16.h>
#include <math.h>
#include <stdint.h>

#define BB 256
#define TT 64
#define HH 1024
#define GG 4096
#define VV 128
#define LL 32

// ---------------- device state (no allocations allowed) ----------------
__device__ __align__(16) float d_hbuf[2][BB * HH];           // fp32 h
__device__ __align__(16) __nv_bfloat16 d_hbb[2][BB * HH];    // bf16 big part of h
__device__ __align__(16) __nv_bfloat16 d_hsb[2][BB * HH];    // bf16 residual of h
__device__ __align__(16) float d_cbuf[BB * HH];
__device__ __align__(16) float d_encX[VV * GG];              // [v][ku*4+g] = emb@W + b
__device__ __align__(16) float d_decX[VV * GG];
__device__ int d_tok[BB];
__device__ __align__(16) __nv_bfloat16 d_Ubb[2][(size_t)GG * HH];  // [which][pc][k] big
__device__ __align__(16) __nv_bfloat16 d_Usb[2][(size_t)GG * HH];  // residual

// ---------------- helpers ----------------
__device__ __forceinline__ float sigmoidf_(float x) { return 1.0f / (1.0f + __expf(-x)); }
__device__ __forceinline__ float tanhf_(float x) {
    float a = fabsf(x);
    float e = __expf(2.0f * a);
    return copysignf(1.0f - 2.0f / (e + 1.0f), x);
}
__device__ __forceinline__ uint32_t smem_u32(const void* p) {
    uint32_t a;
    asm("{ .reg .u64 t; cvta.to.shared.u64 t, %1; cvt.u32.u64 %0, t; }" : "=r"(a) : "l"(p));
    return a;
}
__device__ __forceinline__ void cpasync16(uint32_t dst, const void* src) {
    asm volatile("cp.async.cg.shared.global [%0], [%1], 16;"
                 :: "r"(dst), "l"(__cvta_generic_to_global(src)) : "memory");
}
// NOTE: non-volatile on purpose — pure register op; lets ptxas interleave with LDSM.
// Per-accumulator RAW chains still enforce FP order -> bitwise-identical result.
__device__ __forceinline__ void mma16816(float* c, const uint32_t* a, const uint32_t* b) {
    asm("mma.sync.aligned.m16n8k16.row.col.f32.bf16.bf16.f32 "
        "{%0,%1,%2,%3}, {%4,%5,%6,%7}, {%8,%9}, {%0,%1,%2,%3};"
        : "+f"(c[0]), "+f"(c[1]), "+f"(c[2]), "+f"(c[3])
        : "r"(a[0]), "r"(a[1]), "r"(a[2]), "r"(a[3]), "r"(b[0]), "r"(b[1]));
}
// non-volatile but "memory"-clobbered: cannot cross barriers, can move among MMAs.
__device__ __forceinline__ void ldsm4(uint32_t* r, uint32_t addr) {
    asm("ldmatrix.sync.aligned.m8n8.x4.shared.b16 {%0,%1,%2,%3}, [%4];"
        : "=r"(r[0]), "=r"(r[1]), "=r"(r[2]), "=r"(r[3]) : "r"(addr) : "memory");
}

// ---------------- init ----------------
__global__ void init_kernel() {
    int n = BB * HH;
    __nv_bfloat16 z = __float2bfloat16(0.0f);
    for (int i = blockIdx.x * blockDim.x + threadIdx.x; i < n; i += gridDim.x * blockDim.x) {
        d_hbuf[0][i] = 0.0f;
        d_hbb[0][i] = z;
        d_hsb[0][i] = z;
        d_cbuf[i] = 0.0f;
    }
    if (blockIdx.x == 0 && threadIdx.x < BB) d_tok[threadIdx.x] = VV - 1;
}

// ---------------- table: Xp[v][ku*4+g] = emb[v]@W[:,g*1024+ku] + b ----------------
__global__ __launch_bounds__(256, 1) void table_kernel(
    const float* __restrict__ emb, const float* __restrict__ W,
    const float* __restrict__ bias, int which) {
    float* Xp = which ? d_decX : d_encX;
    __shared__ __align__(16) float semb[32][VV];
    int tid = threadIdx.x;
    int c = blockIdx.x * 32 + (tid & 31);
    int vg = tid >> 5;
    float acc[16];
#pragma unroll
    for (int j = 0; j < 16; j++) acc[j] = 0.0f;
    for (int r0 = 0; r0 < HH; r0 += 32) {
#pragma unroll
        for (int j = 0; j < 4; j++) {
            int idx4 = tid + 256 * j;
            int v = idx4 >> 3, rq = idx4 & 7;
            float4 t4 = *(const float4*)&emb[(size_t)v * HH + r0 + (rq << 2)];
            semb[(rq << 2) + 0][v] = t4.x;
            semb[(rq << 2) + 1][v] = t4.y;
            semb[(rq << 2) + 2][v] = t4.z;
            semb[(rq << 2) + 3][v] = t4.w;
        }
        __syncthreads();
#pragma unroll 8
        for (int r = 0; r < 32; r++) {
            float w = W[(size_t)(r0 + r) * GG + c];
            const float* sp = &semb[r][vg << 4];
#pragma unroll
            for (int j = 0; j < 16; j++) acc[j] += sp[j] * w;
        }
        __syncthreads();
    }
    int k = c & (HH - 1), g = c >> 10;
    float bv = bias[c];
#pragma unroll
    for (int j = 0; j < 16; j++) {
        int v = (vg << 4) + j;
        Xp[(size_t)v * GG + (k << 2) + g] = acc[j] + bv;
    }
}

// ---------------- pack U: Upk[ku*4+g][k] = U[k][g*1024+ku], bf16 split ----------------
__global__ __launch_bounds__(256, 4) void pack_kernel(const float* __restrict__ U, int which) {
    __shared__ float s[32][33];
    int tid = threadIdx.x;
    int k0 = blockIdx.x * 32;
    int c0 = blockIdx.y * 32;
#pragma unroll
    for (int j = 0; j < 4; j++) {
        int idx = tid + 256 * j;
        int r = idx >> 5, ci = idx & 31;
        s[r][ci] = U[(size_t)(k0 + r) * GG + c0 + ci];
    }
    __syncthreads();
    int g = c0 >> 10;
    int ku0 = c0 & (HH - 1);
    __nv_bfloat16* Ub = d_Ubb[which];
    __nv_bfloat16* Us = d_Usb[which];
#pragma unroll
    for (int j = 0; j < 4; j++) {
        int idx = tid + 256 * j;
        int ci = idx >> 5, r = idx & 31;
        float v = s[r][ci];
        __nv_bfloat16 bp = __float2bfloat16(v);
        size_t o = (size_t)((ku0 + ci) * 4 + g) * HH + (k0 + r);
        Ub[o] = bp;
        Us[o] = __float2bfloat16(v - __bfloat162float(bp));
    }
}

// ---------------- mma LSTM step (R13 shape + 3-stage cp.async pipeline) ----------------
// grid (64,2), 512 threads = 16 warps (4m x 4n), warp tile 32(M)x16(N packed).
// CTA: M=128 x N=64 packed; K=1024 in 16 chunks of 64, triple-buffered smem.
// z = hb@Ub + hb@Us + hs@Ub (bf16x3).
#define RSTR  72           // bf16 per smem row (144B: 16B-aligned, conflict-free rotation)
#define RSTRB 144
#define OFS_AB 0u
#define OFS_AS 18432u
#define OFS_BBG 36864u
#define OFS_BS 46080u
#define BUFSZ  55296u
#define NBUF   3
#define OFS_TOK 165888u
#define SMEM_BYTES 166400
#define NCHUNK 16
#define ZSTR 68            // z epilogue stride (floats)

__device__ __forceinline__ void stage_chunk(
    uint32_t sb, int buf, int kc, int tid,
    const __nv_bfloat16* hb, const __nv_bfloat16* hs,
    const __nv_bfloat16* Ub, const __nv_bfloat16* Us, int bm0, int bn0) {
    uint32_t base = sb + buf * BUFSZ;
    int kofs = kc * 64;
#pragma unroll
    for (int j = 0; j < 2; j++) {               // A: 128 rows x 128B per part
        int idx = tid + 512 * j;
        int row = idx >> 3, c = idx & 7;
        uint32_t d = (uint32_t)(row * RSTRB + c * 16);
        size_t go = (size_t)(bm0 + row) * HH + kofs + c * 8;
        cpasync16(base + OFS_AB + d, hb + go);
        cpasync16(base + OFS_AS + d, hs + go);
    }
    {                                           // B: 64 rows x 128B per part
        int row = tid >> 3, c = tid & 7;
        uint32_t d = (uint32_t)(row * RSTRB + c * 16);
        size_t go = (size_t)(bn0 + row) * HH + kofs + c * 8;
        cpasync16(base + OFS_BBG + d, Ub + go);
        cpasync16(base + OFS_BS + d, Us + go);
    }
}

__global__ __launch_bounds__(512, 1) void lstm_mma_kernel(
    int which, const int* __restrict__ tokptr, int tokstride, int tok_mode, int parity) {
    extern __shared__ char smem[];
    uint32_t sb = smem_u32(smem);
    int tid = threadIdx.x;
    int wid = tid >> 5, lane = tid & 31;
    int wm = wid & 3, wn = wid >> 2;            // 4m x 4n; warp tile rows wm*32, cols wn*16
    int bn0 = blockIdx.x * 64;
    int bm0 = blockIdx.y * 128;

    const __nv_bfloat16* hb = d_hbb[parity];
    const __nv_bfloat16* hs = d_hsb[parity];
    const __nv_bfloat16* Ub = d_Ubb[which];
    const __nv_bfloat16* Us = d_Usb[which];
    int* stok = (int*)(smem + OFS_TOK);

    if (tid < 128)
        stok[tid] = tok_mode ? d_tok[bm0 + tid] : tokptr[(size_t)(bm0 + tid) * tokstride];

    float acc[2][2][4];
#pragma unroll
    for (int mt = 0; mt < 2; mt++)
#pragma unroll
        for (int np = 0; np < 2; np++)
#pragma unroll
            for (int r = 0; r < 4; r++) acc[mt][np][r] = 0.0f;

    // ldmatrix lane bases (canonical x4 mapping)
    uint32_t a_base = sb + OFS_AB +
        (uint32_t)((wm * 32 + (lane & 15)) * RSTRB + (lane >> 4) * 16);
    // B: one ldsm4 covers 16 n-rows x 16 k
    uint32_t b_base = sb + OFS_BBG +
        (uint32_t)((wn * 16 + ((lane >> 4) << 3) + (lane & 7)) * RSTRB + ((lane >> 3) & 1) * 16);

    stage_chunk(sb, 0, 0, tid, hb, hs, Ub, Us, bm0, bn0);
    asm volatile("cp.async.commit_group;" ::: "memory");
    stage_chunk(sb, 1, 1, tid, hb, hs, Ub, Us, bm0, bn0);
    asm volatile("cp.async.commit_group;" ::: "memory");

    int cbuf = 0, nbuf2 = 2;
    for (int i = 0; i < NCHUNK; i++) {
        if (i < NCHUNK - 1) {
            asm volatile("cp.async.wait_group 1;" ::: "memory");  // chunk i arrived
        } else {
            asm volatile("cp.async.wait_group 0;" ::: "memory");
        }
        __syncthreads();   // also: all warps done computing chunk i-1 -> buf (i+2)%3 free
        if (i + 2 < NCHUNK) {
            stage_chunk(sb, nbuf2, i + 2, tid, hb, hs, Ub, Us, bm0, bn0);
            asm volatile("cp.async.commit_group;" ::: "memory");
        }
        uint32_t bofs = (uint32_t)(cbuf * BUFSZ);
#pragma unroll
        for (int ks = 0; ks < 4; ks++) {
            uint32_t ka = bofs + ks * 32;
            uint32_t ab[2][4], as2[2][4], bb[4], bs[4];
            ldsm4(ab[0],  a_base + ka);
            ldsm4(ab[1],  a_base + ka + 16 * RSTRB);
            ldsm4(as2[0], a_base + ka + (OFS_AS - OFS_AB));
            ldsm4(as2[1], a_base + ka + (OFS_AS - OFS_AB) + 16 * RSTRB);
            ldsm4(bb, b_base + ka);
            ldsm4(bs, b_base + ka + (OFS_BS - OFS_BBG));
            // term-major: 4 distinct accumulators between reuses
#pragma unroll
            for (int mt = 0; mt < 2; mt++)
#pragma unroll
                for (int np = 0; np < 2; np++)
                    mma16816(acc[mt][np], ab[mt], &bb[np * 2]);
#pragma unroll
            for (int mt = 0; mt < 2; mt++)
#pragma unroll
                for (int np = 0; np < 2; np++)
                    mma16816(acc[mt][np], ab[mt], &bs[np * 2]);
#pragma unroll
            for (int mt = 0; mt < 2; mt++)
#pragma unroll
                for (int np = 0; np < 2; np++)
                    mma16816(acc[mt][np], as2[mt], &bb[np * 2]);
        }
        cbuf = (cbuf + 1) % NBUF;
        nbuf2 = (nbuf2 + 1) % NBUF;
    }

    // ---- epilogue: z -> smem -> gates ----
    float* z = (float*)smem;   // 128 x ZSTR floats = 34816 B (buffer region, dead now)
    int gq = lane >> 2, tq = lane & 3;
    __syncthreads();
#pragma unroll
    for (int mt = 0; mt < 2; mt++) {
        int row0 = wm * 32 + mt * 16 + gq;
#pragma unroll
        for (int np = 0; np < 2; np++) {
            int col = wn * 16 + np * 8 + 2 * tq;
            *(float2*)&z[row0 * ZSTR + col] = make_float2(acc[mt][np][0], acc[mt][np][1]);
            *(float2*)&z[(row0 + 8) * ZSTR + col] = make_float2(acc[mt][np][2], acc[mt][np][3]);
        }
    }
    __syncthreads();

    int row = tid & 127;
    int ublk = tid >> 7;                 // 0..3 -> units ublk*4 .. +3
    int b = bm0 + row;
    int tok = stok[row];
    const float* Xp = which ? d_decX : d_encX;
    const float* hin = d_hbuf[parity];
    float* hout = d_hbuf[parity ^ 1];
    __nv_bfloat16* hbo = d_hbb[parity ^ 1];
    __nv_bfloat16* hso = d_hsb[parity ^ 1];

    if (tok != 0) {
#pragma unroll
        for (int j = 0; j < 4; j++) {
            int u = ublk * 4 + j;
            int kg = (bn0 >> 2) + u;
            float4 zv = *(const float4*)&z[row * ZSTR + u * 4];
            float4 xv = *(const float4*)&Xp[(size_t)tok * GG + bn0 + u * 4];
            float zi = zv.x + xv.x, zf = zv.y + xv.y;
            float zg = zv.z + xv.z, zo = zv.w + xv.w;
            size_t off = (size_t)b * HH + kg;
            float c2 = sigmoidf_(zf) * d_cbuf[off] + sigmoidf_(zi) * tanhf_(zg);
            float h2 = sigmoidf_(zo) * tanhf_(c2);
            d_cbuf[off] = c2;
            hout[off] = h2;
            __nv_bfloat16 hb1 = __float2bfloat16(h2);
            hbo[off] = hb1;
            hso[off] = __float2bfloat16(h2 - __bfloat162float(hb1));
        }
    } else {
#pragma unroll
        for (int j = 0; j < 4; j++) {
            int u = ublk * 4 + j;
            size_t off = (size_t)b * HH + (bn0 >> 2) + u;
            float h2 = hin[off];
            hout[off] = h2;
            __nv_bfloat16 hb1 = __float2bfloat16(h2);
            hbo[off] = hb1;
            hso[off] = __float2bfloat16(h2 - __bfloat162float(hb1));
        }
    }
}

// ---------------- decoder output: logits -> softmax -> argmax ----------------
__global__ __launch_bounds__(256, 2) void dec_out_kernel(
    const float* __restrict__ outW, const float* __restrict__ outb,
    float* __restrict__ dout, int out_size, int t, int parity) {
    const float* __restrict__ h = d_hbuf[parity];
    __shared__ __align__(16) float sh[4][HH];
    __shared__ float slog[4][VV];
    __shared__ float sexp[4][VV];
    __shared__ float ssum[4];
    __shared__ int   stk[4];

    int tid = threadIdx.x;
    int b0 = blockIdx.x * 4;
#pragma unroll
    for (int j = 0; j < 4; j++) {
        int idx4 = tid + 256 * j;
        int row = idx4 >> 8, c4 = idx4 & 255;
        *(float4*)&sh[row][c4 << 2] = *(const float4*)&h[(size_t)(b0 + row) * HH + (c4 << 2)];
    }
    __syncthreads();

    int v = tid & 127, half = tid >> 7;
    float a0 = 0.0f, a1 = 0.0f;
    const float* s0 = sh[half * 2];
    const float* s1 = sh[half * 2 + 1];
#pragma unroll 8
    for (int k = 0; k < HH; k++) {
        float w = outW[(size_t)k * VV + v];
        a0 += s0[k] * w;
        a1 += s1[k] * w;
    }
    float bv = outb[v];
    slog[half * 2][v]     = a0 + bv;
    slog[half * 2 + 1][v] = a1 + bv;
    __syncthreads();

    if (tid < 128) {
        int rw = tid >> 5, lane = tid & 31;
        float m = -3.4e38f; int am = VV;
#pragma unroll
        for (int i = 0; i < 4; i++) {
            int vv = lane + (i << 5);
            float x = slog[rw][vv];
            if (x > m || (x == m && vv < am)) { m = x; am = vv; }
        }
#pragma unroll
        for (int off = 16; off; off >>= 1) {
            float om = __shfl_down_sync(0xffffffffu, m, off);
            int   oa = __shfl_down_sync(0xffffffffu, am, off);
            if (om > m || (om == m && oa < am)) { m = om; am = oa; }
        }
        m  = __shfl_sync(0xffffffffu, m, 0);
        am = __shfl_sync(0xffffffffu, am, 0);
        float s = 0.0f;
#pragma unroll
        for (int i = 0; i < 4; i++) {
            int vv = lane + (i << 5);
            float e = __expf(slog[rw][vv] - m);
            sexp[rw][vv] = e;
            s += e;
        }
#pragma unroll
        for (int off = 16; off; off >>= 1) s += __shfl_xor_sync(0xffffffffu, s, off);
        if (lane == 0) { ssum[rw] = s; stk[rw] = am; d_tok[b0 + rw] = am; }
    }
    __syncthreads();
#pragma unroll
    for (int j = 0; j < 2; j++) {
        int idx = tid + 256 * j;
        int rw = idx >> 7, vv = idx & 127;
        dout[((size_t)(b0 + rw) * LL + t) * VV + vv] = sexp[rw][vv] / ssum[rw];
    }
    if (out_size >= BB * LL * VV + LL * BB && tid < 4) {
        dout[(size_t)BB * LL * VV + (size_t)t * BB + (b0 + tid)] = (float)stk[tid];
    }
}

// ---------------- launcher ----------------
extern "C" void kernel_launch(void* const* d_in, const int* in_sizes, int n_in,
                              void* d_out, int out_size) {
    int idx = 0;
    const int* inputs = (const int*)d_in[idx++];
    if (idx < n_in && in_sizes[idx] == 1) idx++;  // skip max_len scalar if present
    const float* enc_emb = (const float*)d_in[idx++];
    const float* enc_W   = (const float*)d_in[idx++];
    const float* enc_U   = (const float*)d_in[idx++];
    const float* enc_b   = (const float*)d_in[idx++];
    const float* dec_emb = (const float*)d_in[idx++];
    const float* dec_W   = (const float*)d_in[idx++];
    const float* dec_U   = (const float*)d_in[idx++];
    const float* dec_b   = (const float*)d_in[idx++];
    const float* out_W   = (const float*)d_in[idx++];
    const float* out_b   = (const float*)d_in[idx++];
    float* dout = (float*)d_out;

    cudaFuncSetAttribute(lstm_mma_kernel, cudaFuncAttributeMaxDynamicSharedMemorySize,
                         SMEM_BYTES);

    init_kernel<<<256, 256>>>();
    table_kernel<<<128, 256>>>(enc_emb, enc_W, enc_b, 0);
    table_kernel<<<128, 256>>>(dec_emb, dec_W, dec_b, 1);
    pack_kernel<<<dim3(32, 128), 256>>>(enc_U, 0);
    pack_kernel<<<dim3(32, 128), 256>>>(dec_U, 1);

    dim3 grid(64, 2);
    int par = 0;
    for (int t = 0; t < TT; t++) {
        lstm_mma_kernel<<<grid, 512, SMEM_BYTES>>>(0, inputs + t, TT, 0, par);
        par ^= 1;
    }
    for (int s = 0; s < LL; s++) {
        lstm_mma_kernel<<<grid, 512, SMEM_BYTES>>>(1, (const int*)0, 1, 1, par);
        par ^= 1;
        dec_out_kernel<<<64, 256>>>(out_W, out_b, dout, out_size, s, par);
    }
}

// round 17
// speedup vs baseline: 1.1265x; 1.0249x over previous
#include <cuda_runtime.h>
#include <cuda_bf16.h>
#include <math.h>
#include <stdint.h>

#define BB 256
#define TT 64
#define HH 1024
#define GG 4096
#define VV 128
#define LL 32

// ---------------- device state (no allocations allowed) ----------------
__device__ __align__(16) float d_hbuf[2][BB * HH];           // fp32 h
__device__ __align__(16) __nv_bfloat16 d_hbb[2][BB * HH];    // bf16 big part of h
__device__ __align__(16) __nv_bfloat16 d_hsb[2][BB * HH];    // bf16 residual of h
__device__ __align__(16) float d_cbuf[BB * HH];
__device__ __align__(16) float d_encX[VV * GG];              // [v][ku*4+g] = emb@W + b
__device__ __align__(16) float d_decX[VV * GG];
__device__ int d_tok[BB];
__device__ int d_bar;                                        // global barrier counter
__device__ __align__(16) __nv_bfloat16 d_Ubb[2][(size_t)GG * HH];  // [which][pc][k] big
__device__ __align__(16) __nv_bfloat16 d_Usb[2][(size_t)GG * HH];  // residual

// ---------------- helpers ----------------
__device__ __forceinline__ float sigmoidf_(float x) { return 1.0f / (1.0f + __expf(-x)); }
__device__ __forceinline__ float tanhf_(float x) {
    float a = fabsf(x);
    float e = __expf(2.0f * a);
    return copysignf(1.0f - 2.0f / (e + 1.0f), x);
}
__device__ __forceinline__ uint32_t smem_u32(const void* p) {
    uint32_t a;
    asm("{ .reg .u64 t; cvta.to.shared.u64 t, %1; cvt.u32.u64 %0, t; }" : "=r"(a) : "l"(p));
    return a;
}
__device__ __forceinline__ void cpasync16(uint32_t dst, const void* src) {
    asm volatile("cp.async.cg.shared.global [%0], [%1], 16;"
                 :: "r"(dst), "l"(__cvta_generic_to_global(src)) : "memory");
}
__device__ __forceinline__ void mma16816(float* c, const uint32_t* a, const uint32_t* b) {
    asm volatile(
        "mma.sync.aligned.m16n8k16.row.col.f32.bf16.bf16.f32 "
        "{%0,%1,%2,%3}, {%4,%5,%6,%7}, {%8,%9}, {%0,%1,%2,%3};"
        : "+f"(c[0]), "+f"(c[1]), "+f"(c[2]), "+f"(c[3])
        : "r"(a[0]), "r"(a[1]), "r"(a[2]), "r"(a[3]), "r"(b[0]), "r"(b[1]));
}
__device__ __forceinline__ void ldsm4(uint32_t* r, uint32_t addr) {
    asm volatile("ldmatrix.sync.aligned.m8n8.x4.shared.b16 {%0,%1,%2,%3}, [%4];"
                 : "=r"(r[0]), "=r"(r[1]), "=r"(r[2]), "=r"(r[3]) : "r"(addr));
}
// Global barrier: call with all 128 CTAs resident. Pattern: sync; tid0 fence+add+spin; sync.
__device__ __forceinline__ void gbar(int tid, int target) {
    __syncthreads();
    if (tid == 0) {
        __threadfence();
        atomicAdd(&d_bar, 1);
        int v;
        do {
            asm volatile("nanosleep.u32 64;");
            asm volatile("ld.global.acquire.gpu.b32 %0, [%1];"
                         : "=r"(v) : "l"(&d_bar));
        } while (v < target);
    }
    __syncthreads();
}

// ---------------- init ----------------
__global__ void init_kernel() {
    int n = BB * HH;
    __nv_bfloat16 z = __float2bfloat16(0.0f);
    for (int i = blockIdx.x * blockDim.x + threadIdx.x; i < n; i += gridDim.x * blockDim.x) {
        d_hbuf[0][i] = 0.0f;
        d_hbb[0][i] = z;
        d_hsb[0][i] = z;
        d_cbuf[i] = 0.0f;
    }
    if (blockIdx.x == 0 && threadIdx.x < BB) d_tok[threadIdx.x] = VV - 1;
    if (blockIdx.x == 0 && threadIdx.x == 0) d_bar = 0;
}

// ---------------- table: Xp[v][ku*4+g] = emb[v]@W[:,g*1024+ku] + b ----------------
__global__ __launch_bounds__(256, 1) void table_kernel(
    const float* __restrict__ emb, const float* __restrict__ W,
    const float* __restrict__ bias, int which) {
    float* Xp = which ? d_decX : d_encX;
    __shared__ __align__(16) float semb[32][VV];
    int tid = threadIdx.x;
    int c = blockIdx.x * 32 + (tid & 31);
    int vg = tid >> 5;
    float acc[16];
#pragma unroll
    for (int j = 0; j < 16; j++) acc[j] = 0.0f;
    for (int r0 = 0; r0 < HH; r0 += 32) {
#pragma unroll
        for (int j = 0; j < 4; j++) {
            int idx4 = tid + 256 * j;
            int v = idx4 >> 3, rq = idx4 & 7;
            float4 t4 = *(const float4*)&emb[(size_t)v * HH + r0 + (rq << 2)];
            semb[(rq << 2) + 0][v] = t4.x;
            semb[(rq << 2) + 1][v] = t4.y;
            semb[(rq << 2) + 2][v] = t4.z;
            semb[(rq << 2) + 3][v] = t4.w;
        }
        __syncthreads();
#pragma unroll 8
        for (int r = 0; r < 32; r++) {
            float w = W[(size_t)(r0 + r) * GG + c];
            const float* sp = &semb[r][vg << 4];
#pragma unroll
            for (int j = 0; j < 16; j++) acc[j] += sp[j] * w;
        }
        __syncthreads();
    }
    int k = c & (HH - 1), g = c >> 10;
    float bv = bias[c];
#pragma unroll
    for (int j = 0; j < 16; j++) {
        int v = (vg << 4) + j;
        Xp[(size_t)v * GG + (k << 2) + g] = acc[j] + bv;
    }
}

// ---------------- pack U: Upk[ku*4+g][k] = U[k][g*1024+ku], bf16 split ----------------
__global__ __launch_bounds__(256, 4) void pack_kernel(const float* __restrict__ U, int which) {
    __shared__ float s[32][33];
    int tid = threadIdx.x;
    int k0 = blockIdx.x * 32;
    int c0 = blockIdx.y * 32;
#pragma unroll
    for (int j = 0; j < 4; j++) {
        int idx = tid + 256 * j;
        int r = idx >> 5, ci = idx & 31;
        s[r][ci] = U[(size_t)(k0 + r) * GG + c0 + ci];
    }
    __syncthreads();
    int g = c0 >> 10;
    int ku0 = c0 & (HH - 1);
    __nv_bfloat16* Ub = d_Ubb[which];
    __nv_bfloat16* Us = d_Usb[which];
#pragma unroll
    for (int j = 0; j < 4; j++) {
        int idx = tid + 256 * j;
        int ci = idx >> 5, r = idx & 31;
        float v = s[r][ci];
        __nv_bfloat16 bp = __float2bfloat16(v);
        size_t o = (size_t)((ku0 + ci) * 4 + g) * HH + (k0 + r);
        Ub[o] = bp;
        Us[o] = __float2bfloat16(v - __bfloat162float(bp));
    }
}

// ---------------- persistent LSTM: all 96 steps + decoder output, one kernel ----------
// grid (64,2) = 128 CTAs (1/SM, all resident), 512 threads = 16 warps (4m x 4n).
// CTA tile: M=128 x N=64 packed; K=1024 in 16 chunks of 64 (R13 mainloop, unchanged).
#define RSTR  72
#define RSTRB 144
#define OFS_AB 0u
#define OFS_AS 18432u
#define OFS_BBG 36864u
#define OFS_BS 46080u
#define BUFSZ  55296u
#define OFS_TOK 110592u
#define SMEM_BYTES 111616
#define ZSTR 68

__device__ __forceinline__ void stage_chunk(
    uint32_t sb, int buf, int kc, int tid,
    const __nv_bfloat16* hb, const __nv_bfloat16* hs,
    const __nv_bfloat16* Ub, const __nv_bfloat16* Us, int bm0, int bn0) {
    uint32_t base = sb + buf * BUFSZ;
    int kofs = kc * 64;
#pragma unroll
    for (int j = 0; j < 2; j++) {               // A: 128 rows x 128B per part
        int idx = tid + 512 * j;
        int row = idx >> 3, c = idx & 7;
        uint32_t d = (uint32_t)(row * RSTRB + c * 16);
        size_t go = (size_t)(bm0 + row) * HH + kofs + c * 8;
        cpasync16(base + OFS_AB + d, hb + go);
        cpasync16(base + OFS_AS + d, hs + go);
    }
    {                                           // B: 64 rows x 128B per part
        int row = tid >> 3, c = tid & 7;
        uint32_t d = (uint32_t)(row * RSTRB + c * 16);
        size_t go = (size_t)(bn0 + row) * HH + kofs + c * 8;
        cpasync16(base + OFS_BBG + d, Ub + go);
        cpasync16(base + OFS_BS + d, Us + go);
    }
}

__global__ __launch_bounds__(512, 1) void lstm_persist_kernel(
    const int* __restrict__ inputs, const float* __restrict__ outW,
    const float* __restrict__ outb, float* __restrict__ dout, int out_size) {
    extern __shared__ char smem[];
    uint32_t sb = smem_u32(smem);
    int tid = threadIdx.x;
    int wid = tid >> 5, lane = tid & 31;
    int wm = wid & 3, wn = wid >> 2;
    int bn0 = blockIdx.x * 64;
    int bm0 = blockIdx.y * 128;
    int cid = blockIdx.y * 64 + blockIdx.x;      // 0..127
    int* stok = (int*)(smem + OFS_TOK);

    uint32_t a_base = sb + OFS_AB +
        (uint32_t)((wm * 32 + (lane & 15)) * RSTRB + (lane >> 4) * 16);
    uint32_t b_base = sb + OFS_BBG +
        (uint32_t)((wn * 16 + ((lane >> 4) << 3) + (lane & 7)) * RSTRB + ((lane >> 3) & 1) * 16);

    int gq = lane >> 2, tq = lane & 3;
    int barcnt = 0;
    int par = 0;

    for (int step = 0; step < TT + LL; step++) {
        int isdec = (step >= TT) ? 1 : 0;
        const __nv_bfloat16* hb = d_hbb[par];
        const __nv_bfloat16* hs = d_hsb[par];
        const __nv_bfloat16* Ub = d_Ubb[isdec];
        const __nv_bfloat16* Us = d_Usb[isdec];

        if (tid < 128)
            stok[tid] = isdec ? d_tok[bm0 + tid]
                              : inputs[(size_t)(bm0 + tid) * TT + step];

        float acc[2][2][4];
#pragma unroll
        for (int mt = 0; mt < 2; mt++)
#pragma unroll
            for (int np = 0; np < 2; np++)
#pragma unroll
                for (int r = 0; r < 4; r++) acc[mt][np][r] = 0.0f;

        stage_chunk(sb, 0, 0, tid, hb, hs, Ub, Us, bm0, bn0);
        asm volatile("cp.async.commit_group;" ::: "memory");

        for (int i = 0; i < 16; i++) {
            asm volatile("cp.async.wait_group 0;" ::: "memory");
            __syncthreads();
            if (i + 1 < 16) {
                stage_chunk(sb, (i + 1) & 1, i + 1, tid, hb, hs, Ub, Us, bm0, bn0);
                asm volatile("cp.async.commit_group;" ::: "memory");
            }
            uint32_t bofs = (uint32_t)((i & 1) * BUFSZ);
#pragma unroll
            for (int ks = 0; ks < 4; ks++) {
                uint32_t ka = bofs + ks * 32;
                uint32_t ab[2][4], as2[2][4], bbf[4], bsf[4];
                ldsm4(ab[0],  a_base + ka);
                ldsm4(ab[1],  a_base + ka + 16 * RSTRB);
                ldsm4(as2[0], a_base + ka + (OFS_AS - OFS_AB));
                ldsm4(as2[1], a_base + ka + (OFS_AS - OFS_AB) + 16 * RSTRB);
                ldsm4(bbf, b_base + ka);
                ldsm4(bsf, b_base + ka + (OFS_BS - OFS_BBG));
#pragma unroll
                for (int mt = 0; mt < 2; mt++)
#pragma unroll
                    for (int np = 0; np < 2; np++)
                        mma16816(acc[mt][np], ab[mt], &bbf[np * 2]);
#pragma unroll
                for (int mt = 0; mt < 2; mt++)
#pragma unroll
                    for (int np = 0; np < 2; np++)
                        mma16816(acc[mt][np], ab[mt], &bsf[np * 2]);
#pragma unroll
                for (int mt = 0; mt < 2; mt++)
#pragma unroll
                    for (int np = 0; np < 2; np++)
                        mma16816(acc[mt][np], as2[mt], &bbf[np * 2]);
            }
        }

        // ---- epilogue: z -> smem -> gates ----
        float* z = (float*)smem;
        __syncthreads();
#pragma unroll
        for (int mt = 0; mt < 2; mt++) {
            int row0 = wm * 32 + mt * 16 + gq;
#pragma unroll
            for (int np = 0; np < 2; np++) {
                int col = wn * 16 + np * 8 + 2 * tq;
                *(float2*)&z[row0 * ZSTR + col] = make_float2(acc[mt][np][0], acc[mt][np][1]);
                *(float2*)&z[(row0 + 8) * ZSTR + col] = make_float2(acc[mt][np][2], acc[mt][np][3]);
            }
        }
        __syncthreads();

        {
            int row = tid & 127;
            int ublk = tid >> 7;
            int b = bm0 + row;
            int tok = stok[row];
            const float* Xp = isdec ? d_decX : d_encX;
            const float* hin = d_hbuf[par];
            float* hout = d_hbuf[par ^ 1];
            __nv_bfloat16* hbo = d_hbb[par ^ 1];
            __nv_bfloat16* hso = d_hsb[par ^ 1];

            if (tok != 0) {
#pragma unroll
                for (int j = 0; j < 4; j++) {
                    int u = ublk * 4 + j;
                    int kg = (bn0 >> 2) + u;
                    float4 zv = *(const float4*)&z[row * ZSTR + u * 4];
                    float4 xv = *(const float4*)&Xp[(size_t)tok * GG + bn0 + u * 4];
                    float zi = zv.x + xv.x, zf = zv.y + xv.y;
                    float zg = zv.z + xv.z, zo = zv.w + xv.w;
                    size_t off = (size_t)b * HH + kg;
                    float c2 = sigmoidf_(zf) * d_cbuf[off] + sigmoidf_(zi) * tanhf_(zg);
                    float h2 = sigmoidf_(zo) * tanhf_(c2);
                    d_cbuf[off] = c2;
                    hout[off] = h2;
                    __nv_bfloat16 hb1 = __float2bfloat16(h2);
                    hbo[off] = hb1;
                    hso[off] = __float2bfloat16(h2 - __bfloat162float(hb1));
                }
            } else {
#pragma unroll
                for (int j = 0; j < 4; j++) {
                    int u = ublk * 4 + j;
                    size_t off = (size_t)b * HH + (bn0 >> 2) + u;
                    float h2 = hin[off];
                    hout[off] = h2;
                    __nv_bfloat16 hb1 = __float2bfloat16(h2);
                    hbo[off] = hb1;
                    hso[off] = __float2bfloat16(h2 - __bfloat162float(hb1));
                }
            }
        }

        barcnt++;
        gbar(tid, barcnt * 128);   // h globally visible

        if (isdec) {
            // ---- dec phase: this CTA handles batch rows 2*cid, 2*cid+1 ----
            int s = step - TT;
            float* sh2  = (float*)smem;                  // 2 x 1024
            float* slog = (float*)(smem + 8192);         // 2 x 128
            float* sexp = (float*)(smem + 9216);         // 2 x 128
            float* ssum = (float*)(smem + 10240);        // 2
            int*   stk2 = (int*)(smem + 10256);          // 2
            const float* hsrc = d_hbuf[par ^ 1];
            int r0 = 2 * cid;

            {   // stage h rows: 512 threads x float4 = 2048 floats
                int row = tid >> 8, c4 = tid & 255;
                *(float4*)&sh2[row * HH + (c4 << 2)] =
                    *(const float4*)&hsrc[(size_t)(r0 + row) * HH + (c4 << 2)];
            }
            __syncthreads();

            if (tid < 256) {   // logits: 2 rows x 128 v
                int row = tid >> 7, v = tid & 127;
                float a = outb[v];
                const float* srow = sh2 + row * HH;
#pragma unroll 8
                for (int k = 0; k < HH; k++) a += srow[k] * outW[(size_t)k * VV + v];
                slog[row * VV + v] = a;
            }
            __syncthreads();

            if (tid < 64) {    // warps 0-1: one row each
                int rw = tid >> 5, ln = tid & 31;
                float m = -3.4e38f; int am = VV;
#pragma unroll
                for (int i = 0; i < 4; i++) {
                    int vv = ln + (i << 5);
                    float x = slog[rw * VV + vv];
                    if (x > m || (x == m && vv < am)) { m = x; am = vv; }
                }
#pragma unroll
                for (int off = 16; off; off >>= 1) {
                    float om = __shfl_down_sync(0xffffffffu, m, off);
                    int   oa = __shfl_down_sync(0xffffffffu, am, off);
                    if (om > m || (om == m && oa < am)) { m = om; am = oa; }
                }
                m  = __shfl_sync(0xffffffffu, m, 0);
                am = __shfl_sync(0xffffffffu, am, 0);
                float sum = 0.0f;
#pragma unroll
                for (int i = 0; i < 4; i++) {
                    int vv = ln + (i << 5);
                    float e = __expf(slog[rw * VV + vv] - m);
                    sexp[rw * VV + vv] = e;
                    sum += e;
                }
#pragma unroll
                for (int off = 16; off; off >>= 1) sum += __shfl_xor_sync(0xffffffffu, sum, off);
                if (ln == 0) {
                    ssum[rw] = sum;
                    stk2[rw] = am;
                    d_tok[r0 + rw] = am;
                }
            }
            __syncthreads();

            if (tid < 256) {
                int row = tid >> 7, v = tid & 127;
                dout[((size_t)(r0 + row) * LL + s) * VV + v] = sexp[row * VV + v] / ssum[row];
            }
            if (out_size >= BB * LL * VV + LL * BB && tid < 2) {
                dout[(size_t)BB * LL * VV + (size_t)s * BB + (r0 + tid)] = (float)stk2[tid];
            }

            barcnt++;
            gbar(tid, barcnt * 128);   // tokens + y globally visible
        }

        par ^= 1;
    }
}

// ---------------- launcher ----------------
extern "C" void kernel_launch(void* const* d_in, const int* in_sizes, int n_in,
                              void* d_out, int out_size) {
    int idx = 0;
    const int* inputs = (const int*)d_in[idx++];
    if (idx < n_in && in_sizes[idx] == 1) idx++;  // skip max_len scalar if present
    const float* enc_emb = (const float*)d_in[idx++];
    const float* enc_W   = (const float*)d_in[idx++];
    const float* enc_U   = (const float*)d_in[idx++];
    const float* enc_b   = (const float*)d_in[idx++];
    const float* dec_emb = (const float*)d_in[idx++];
    const float* dec_W   = (const float*)d_in[idx++];
    const float* dec_U   = (const float*)d_in[idx++];
    const float* dec_b   = (const float*)d_in[idx++];
    const float* out_W   = (const float*)d_in[idx++];
    const float* out_b   = (const float*)d_in[idx++];
    float* dout = (float*)d_out;

    cudaFuncSetAttribute(lstm_persist_kernel, cudaFuncAttributeMaxDynamicSharedMemorySize,
                         SMEM_BYTES);

    init_kernel<<<256, 256>>>();
    table_kernel<<<128, 256>>>(enc_emb, enc_W, enc_b, 0);
    table_kernel<<<128, 256>>>(dec_emb, dec_W, dec_b, 1);
    pack_kernel<<<dim3(32, 128), 256>>>(enc_U, 0);
    pack_kernel<<<dim3(32, 128), 256>>>(dec_U, 1);

    dim3 grid(64, 2);
    lstm_persist_kernel<<<grid, 512, SMEM_BYTES>>>(inputs, out_W, out_b, dout, out_size);
}